// round 5
// baseline (speedup 1.0000x reference)
#include <cuda_runtime.h>
#include <cuda_bf16.h>
#include <cstdint>

// Problem shape (fixed by the dataset)
#define NPTS   4096
#define NS     16384
#define CH     256
#define CSKIP  128
#define DIN    384
#define HID    256
#define BMAX   8

// GEMM tiling
#define BM 128
#define BN 128
#define BK 32
#define SMS 40              // smem row stride (floats): conflict-free float2 frags
#define STAGE (BM * SMS)    // floats per operand per stage

// Scratch (static device globals; no allocation allowed)
__device__ float g_h[NS * HID];        // hidden activations (tf32, k-permuted)
__device__ float g_w1t[HID * DIN];     // W1^T  [N, K] tf32, k-permuted
__device__ float g_w2t[HID * HID];     // W2^T  [N, K] tf32, k-permuted
__device__ int   g_idx[NS * 3];
__device__ float g_w[NS * 3];
__device__ int   g_bstart[BMAX + 1];

// k-permutation within each 8-group: pos(r) puts (tg, tg+4) adjacent
__host__ __device__ __forceinline__ int pp8(int r) {  // r in 0..7
    return (r & 3) * 2 + (r >> 2);
}

// ===========================================================================
// helpers
// ===========================================================================
__device__ __forceinline__ uint32_t smem_u32(const void* p) {
    uint32_t a;
    asm("{ .reg .u64 t; cvta.to.shared.u64 t, %1; cvt.u32.u64 %0, t; }"
        : "=r"(a) : "l"(p));
    return a;
}
__device__ __forceinline__ uint32_t to_tf32(float f) {
    uint32_t u;
    asm("cvt.rna.tf32.f32 %0, %1;" : "=r"(u) : "f"(f));
    return u;
}
__device__ __forceinline__ float tf32f(float f) {
    return __uint_as_float(to_tf32(f));
}
__device__ __forceinline__ void cp16(uint32_t sdst, const void* gsrc) {
    asm volatile("cp.async.ca.shared.global [%0], [%1], 16;"
                 :: "r"(sdst), "l"(gsrc));
}
#define CP_COMMIT() asm volatile("cp.async.commit_group;" ::: "memory")
#define CP_WAIT0()  asm volatile("cp.async.wait_group 0;"  ::: "memory")

__device__ __forceinline__ void mma_tf32(float c[4], const uint32_t a[4],
                                         const uint32_t b[2]) {
    asm volatile(
        "mma.sync.aligned.m16n8k8.row.col.f32.tf32.tf32.f32 "
        "{%0,%1,%2,%3}, {%4,%5,%6,%7}, {%8,%9}, {%0,%1,%2,%3};"
        : "+f"(c[0]), "+f"(c[1]), "+f"(c[2]), "+f"(c[3])
        : "r"(a[0]), "r"(a[1]), "r"(a[2]), "r"(a[3]), "r"(b[0]), "r"(b[1]));
}

// ===========================================================================
// 1) batch segment boundaries (batch is sorted)
// ===========================================================================
__global__ void seg_kernel(const int* __restrict__ batch, int n) {
    int j = blockIdx.x * blockDim.x + threadIdx.x;
    if (j >= n) return;
    int b  = batch[j];
    int bp = (j == 0) ? -1 : batch[j - 1];
    for (int v = bp + 1; v <= b; v++) g_bstart[v] = j;
    if (j == n - 1) {
        for (int v = b + 1; v <= BMAX; v++) g_bstart[v] = n;
    }
}

// ===========================================================================
// 2) kNN (K=3); block loads only the batch-segment range it needs
// ===========================================================================
__global__ void knn_kernel(const float* __restrict__ pos,
                           const float* __restrict__ pos_skip,
                           const int* __restrict__ batch_skip) {
    extern __shared__ float4 s_pts[];
    int tid = threadIdx.x;
    int t0 = blockIdx.x * blockDim.x;

    int qb_first = batch_skip[t0];
    int qb_last  = batch_skip[t0 + blockDim.x - 1];
    int jmin = g_bstart[qb_first];
    int jmax = g_bstart[qb_last + 1];

    for (int j = jmin + tid; j < jmax; j += blockDim.x) {
        float4 p;
        p.x = pos[3 * j + 0];
        p.y = pos[3 * j + 1];
        p.z = pos[3 * j + 2];
        p.w = 0.0f;
        s_pts[j - jmin] = p;
    }
    __syncthreads();

    int t = t0 + tid;
    float qx = pos_skip[3 * t + 0];
    float qy = pos_skip[3 * t + 1];
    float qz = pos_skip[3 * t + 2];
    int   qb = batch_skip[t];
    int j0 = g_bstart[qb] - jmin;
    int j1 = g_bstart[qb + 1] - jmin;

    float b0 = 3.0e38f, b1 = 3.0e38f, b2 = 3.0e38f;
    int   i0 = j0, i1 = j0, i2 = j0;

    #pragma unroll 4
    for (int j = j0; j < j1; j++) {
        float4 p = s_pts[j];
        float dx = p.x - qx;
        float dy = p.y - qy;
        float dz = p.z - qz;
        float d = fmaf(dx, dx, fmaf(dy, dy, dz * dz));
        if (d < b2) {
            if (d < b1) {
                if (d < b0) {
                    b2 = b1; i2 = i1; b1 = b0; i1 = i0; b0 = d; i0 = j;
                } else {
                    b2 = b1; i2 = i1; b1 = d; i1 = j;
                }
            } else {
                b2 = d; i2 = j;
            }
        }
    }

    float w0 = 1.0f / fmaxf(b0, 1e-16f);
    float w1 = 1.0f / fmaxf(b1, 1e-16f);
    float w2 = 1.0f / fmaxf(b2, 1e-16f);
    float inv = 1.0f / (w0 + w1 + w2);
    g_w[3 * t + 0] = w0 * inv;
    g_w[3 * t + 1] = w1 * inv;
    g_w[3 * t + 2] = w2 * inv;
    g_idx[3 * t + 0] = i0 + jmin;
    g_idx[3 * t + 1] = i1 + jmin;
    g_idx[3 * t + 2] = i2 + jmin;
}

// ===========================================================================
// 3) both weight transposes in ONE launch; tf32 round + k-permuted output
//    W[K,N] -> Wt[N, K] with column k stored at perm position
// ===========================================================================
__global__ void transpose_both(const float* __restrict__ W1, float* __restrict__ W1t,
                               const float* __restrict__ W2, float* __restrict__ W2t) {
    __shared__ float tile[32][33];
    const float* W; float* Wt; int K, k0;
    int bx = blockIdx.x;
    if (bx < DIN / 32) { W = W1; Wt = W1t; K = DIN; k0 = bx * 32; }
    else               { W = W2; Wt = W2t; K = HID; k0 = (bx - DIN / 32) * 32; }
    int n0 = blockIdx.y * 32;
    int tx = threadIdx.x, ty = threadIdx.y;
    for (int i = ty; i < 32; i += 8)
        tile[i][tx] = W[(size_t)(k0 + i) * HID + n0 + tx];
    __syncthreads();
    int dcol = k0 + (tx & 24) + pp8(tx & 7);
    for (int i = ty; i < 32; i += 8)
        Wt[(size_t)(n0 + i) * K + dcol] = tf32f(tile[tx][i]);
}

// ===========================================================================
// 4) mma.sync tf32 GEMM + bias + ReLU, k-permuted operands.
//    C[M, 256] = relu(A[M,K] @ Wt^T + bias)
//    FUSED: A built on the fly = [knn-interp(x), x_skip] (tf32, permuted)
//    EPI_PERM: store output k-permuted + tf32 (feeds next GEMM as A)
// ===========================================================================
template<int KTOT, bool FUSED, bool EPI_PERM>
__global__ void __launch_bounds__(256, 2)
gemm_mma(const float* __restrict__ A,
         const float* __restrict__ x,
         const float* __restrict__ xs,
         const float* __restrict__ Wt,
         const float* __restrict__ bias,
         float* __restrict__ C) {
    extern __shared__ float smem[];
    float* sA = smem;                 // [2][STAGE]
    float* sB = smem + 2 * STAGE;     // [2][STAGE]

    const int tid  = threadIdx.x;
    const int wid  = tid >> 5, lane = tid & 31;
    const int gid  = lane >> 2, tg = lane & 3;
    const int wm0  = (wid & 3) * 32;      // 4 warps along M
    const int wn0  = (wid >> 2) * 64;     // 2 warps along N
    const int m0   = blockIdx.x * BM;
    const int n0   = blockIdx.y * BN;

    const int arow  = tid >> 1;           // 0..127
    const int akoff = (tid & 1) * 16;     // half-row k offset (floats)

    int i0 = 0, i1 = 0, i2 = 0;
    float w0 = 0, w1 = 0, w2 = 0;
    if (FUSED) {
        int m = m0 + arow;
        i0 = g_idx[3 * m]; i1 = g_idx[3 * m + 1]; i2 = g_idx[3 * m + 2];
        w0 = g_w[3 * m];   w1 = g_w[3 * m + 1];   w2 = g_w[3 * m + 2];
    }

    float acc[2][8][4];
    #pragma unroll
    for (int mt = 0; mt < 2; mt++)
        #pragma unroll
        for (int nt = 0; nt < 8; nt++)
            #pragma unroll
            for (int q = 0; q < 4; q++) acc[mt][nt][q] = 0.0f;

    constexpr int T = KTOT / BK;

    auto issue = [&](int t) {
        int s  = t & 1;
        int k0 = t * BK;
        float* dA = sA + s * STAGE;
        float* dB = sB + s * STAGE;
        // B tile (already tf32 + permuted in gmem): contiguous cp.async
        {
            const float* src = Wt + (size_t)(n0 + arow) * KTOT + k0 + akoff;
            uint32_t dst = smem_u32(dB + arow * SMS + akoff);
            #pragma unroll
            for (int j = 0; j < 4; j++) cp16(dst + j * 16, src + j * 4);
        }
        // A tile
        if (FUSED) {
            // two 8-groups, built and stored permuted
            #pragma unroll
            for (int g = 0; g < 2; g++) {
                int kb = akoff + g * 8;       // group base within tile
                float v[8];
                #pragma unroll
                for (int h = 0; h < 2; h++) {
                    int kg = k0 + kb + h * 4;
                    float4 vv;
                    if (kg < CH) {
                        float4 a0 = *(const float4*)(x + (size_t)i0 * CH + kg);
                        float4 a1 = *(const float4*)(x + (size_t)i1 * CH + kg);
                        float4 a2 = *(const float4*)(x + (size_t)i2 * CH + kg);
                        vv.x = w0 * a0.x + w1 * a1.x + w2 * a2.x;
                        vv.y = w0 * a0.y + w1 * a1.y + w2 * a2.y;
                        vv.z = w0 * a0.z + w1 * a1.z + w2 * a2.z;
                        vv.w = w0 * a0.w + w1 * a1.w + w2 * a2.w;
                    } else {
                        vv = *(const float4*)(xs + (size_t)(m0 + arow) * CSKIP
                                              + (kg - CH));
                    }
                    v[h * 4 + 0] = vv.x; v[h * 4 + 1] = vv.y;
                    v[h * 4 + 2] = vv.z; v[h * 4 + 3] = vv.w;
                }
                float* d = dA + arow * SMS + kb;
                #pragma unroll
                for (int q = 0; q < 4; q++) {
                    float2 pr;
                    pr.x = tf32f(v[q]);
                    pr.y = tf32f(v[q + 4]);
                    *(float2*)(d + 2 * q) = pr;
                }
            }
        } else {
            // A (g_h) already tf32 + permuted in gmem: contiguous cp.async
            const float* src = A + (size_t)(m0 + arow) * KTOT + k0 + akoff;
            uint32_t dst = smem_u32(dA + arow * SMS + akoff);
            #pragma unroll
            for (int j = 0; j < 4; j++) cp16(dst + j * 16, src + j * 4);
        }
    };

    issue(0);
    CP_COMMIT();

    for (int t = 0; t < T; t++) {
        CP_WAIT0();
        __syncthreads();
        if (t + 1 < T) { issue(t + 1); CP_COMMIT(); }

        int s = t & 1;
        const float* aA = sA + s * STAGE + wm0 * SMS;
        const float* aB = sB + s * STAGE + wn0 * SMS;

        #pragma unroll
        for (int ks = 0; ks < 4; ks++) {
            const int ko = ks * 8 + 2 * tg;
            uint32_t af[2][4];
            #pragma unroll
            for (int mt = 0; mt < 2; mt++) {
                float2 lo = *(const float2*)(aA + (mt * 16 + gid) * SMS + ko);
                float2 hi = *(const float2*)(aA + (mt * 16 + gid + 8) * SMS + ko);
                af[mt][0] = __float_as_uint(lo.x);
                af[mt][1] = __float_as_uint(hi.x);
                af[mt][2] = __float_as_uint(lo.y);
                af[mt][3] = __float_as_uint(hi.y);
            }
            uint32_t bf[8][2];
            #pragma unroll
            for (int nt = 0; nt < 8; nt++) {
                float2 b = *(const float2*)(aB + (nt * 8 + gid) * SMS + ko);
                bf[nt][0] = __float_as_uint(b.x);
                bf[nt][1] = __float_as_uint(b.y);
            }
            #pragma unroll
            for (int mt = 0; mt < 2; mt++)
                #pragma unroll
                for (int nt = 0; nt < 8; nt++)
                    mma_tf32(acc[mt][nt], af[mt], bf[nt]);
        }
    }

    // epilogue: bias + relu; EPI_PERM -> tf32 + k-permuted scatter (feeds GEMM2)
    #pragma unroll
    for (int mt = 0; mt < 2; mt++) {
        int r0 = m0 + wm0 + mt * 16 + gid;
        #pragma unroll
        for (int nt = 0; nt < 8; nt++) {
            int base = n0 + wn0 + nt * 8;
            int col = base + tg * 2;
            float bv0 = __ldg(bias + col);
            float bv1 = __ldg(bias + col + 1);
            float v0 = fmaxf(acc[mt][nt][0] + bv0, 0.0f);
            float v1 = fmaxf(acc[mt][nt][1] + bv1, 0.0f);
            float v2 = fmaxf(acc[mt][nt][2] + bv0, 0.0f);
            float v3 = fmaxf(acc[mt][nt][3] + bv1, 0.0f);
            if (EPI_PERM) {
                int p0 = base + pp8(tg * 2);
                int p1 = base + pp8(tg * 2 + 1);
                C[(size_t)r0 * 256 + p0]       = tf32f(v0);
                C[(size_t)r0 * 256 + p1]       = tf32f(v1);
                C[(size_t)(r0 + 8) * 256 + p0] = tf32f(v2);
                C[(size_t)(r0 + 8) * 256 + p1] = tf32f(v3);
            } else {
                *(float2*)(C + (size_t)r0 * 256 + col)       = make_float2(v0, v1);
                *(float2*)(C + (size_t)(r0 + 8) * 256 + col) = make_float2(v2, v3);
            }
        }
    }
}

// ===========================================================================
// 5) tuple tail: pos_skip + batch_skip (as float)
// ===========================================================================
__global__ void tail_kernel(const float* __restrict__ pos_skip,
                            const int* __restrict__ batch_skip,
                            float* __restrict__ out, int write_batch) {
    int i = blockIdx.x * blockDim.x + threadIdx.x;
    if (i < NS * 3) out[(size_t)NS * HID + i] = pos_skip[i];
    if (write_batch && i < NS)
        out[(size_t)NS * HID + (size_t)NS * 3 + i] = (float)batch_skip[i];
}

// ===========================================================================
extern "C" void kernel_launch(void* const* d_in, const int* in_sizes, int n_in,
                              void* d_out, int out_size) {
    const float* x          = (const float*)d_in[0];
    const float* pos        = (const float*)d_in[1];
    const int*   batch      = (const int*)  d_in[2];
    const float* x_skip     = (const float*)d_in[3];
    const float* pos_skip   = (const float*)d_in[4];
    const int*   batch_skip = (const int*)  d_in[5];
    const float* W1         = (const float*)d_in[6];
    const float* b1         = (const float*)d_in[7];
    const float* W2         = (const float*)d_in[8];
    const float* b2         = (const float*)d_in[9];
    float* out = (float*)d_out;

    float *p_h, *p_w1t, *p_w2t;
    cudaGetSymbolAddress((void**)&p_h,   g_h);
    cudaGetSymbolAddress((void**)&p_w1t, g_w1t);
    cudaGetSymbolAddress((void**)&p_w2t, g_w2t);

    // 1) batch segments
    seg_kernel<<<(NPTS + 255) / 256, 256>>>(batch, NPTS);

    // 2) kNN
    size_t knn_smem = (size_t)NPTS * sizeof(float4);
    cudaFuncSetAttribute(knn_kernel, cudaFuncAttributeMaxDynamicSharedMemorySize,
                         (int)knn_smem);
    knn_kernel<<<NS / 128, 128, knn_smem>>>(pos, pos_skip, batch_skip);

    // 3) both weight transposes (tf32 + permuted), one launch
    {
        dim3 b(32, 8);
        transpose_both<<<dim3(DIN / 32 + HID / 32, HID / 32), b>>>(
            W1, p_w1t, W2, p_w2t);
    }

    // 4) MLP on tensor cores; GEMM1 fuses interpolate+concat
    size_t gsmem = 4 * STAGE * sizeof(float);   // 81920 B
    cudaFuncSetAttribute(gemm_mma<DIN, true, true>,
                         cudaFuncAttributeMaxDynamicSharedMemorySize, (int)gsmem);
    cudaFuncSetAttribute(gemm_mma<HID, false, false>,
                         cudaFuncAttributeMaxDynamicSharedMemorySize, (int)gsmem);
    {
        dim3 grid(NS / BM, HID / BN);
        gemm_mma<DIN, true, true><<<grid, 256, gsmem>>>(
            nullptr, x, x_skip, p_w1t, b1, p_h);
        gemm_mma<HID, false, false><<<grid, 256, gsmem>>>(
            p_h, nullptr, nullptr, p_w2t, b2, out);
    }

    // 5) tuple tail
    long long need_pos   = (long long)NS * HID + (long long)NS * 3;
    long long need_batch = need_pos + NS;
    if ((long long)out_size >= need_pos) {
        int wb = ((long long)out_size >= need_batch) ? 1 : 0;
        tail_kernel<<<(NS * 3 + 255) / 256, 256>>>(pos_skip, batch_skip, out, wb);
    }
    (void)n_in; (void)in_sizes;
}

// round 8
// speedup vs baseline: 1.1289x; 1.1289x over previous
#include <cuda_runtime.h>
#include <cuda_fp16.h>
#include <cstdint>
#include <cstring>

// Problem shape (fixed by the dataset)
#define NPTS   4096
#define NS     16384
#define CH     256
#define CSKIP  128
#define DIN    384
#define HID    256
#define BMAX   8

// GEMM tiling (fp16 mma.m16n8k16)
#define BM 128
#define BN 128
#define BK 64
#define ROWB 144                 // smem row stride in bytes (64 halfs + 8 pad)
#define STAGEB (BM * ROWB)       // 18432 B per operand per stage
#define SMEM_GEMM (4 * STAGEB)   // 73728 B

// Scratch (static device globals; no allocation allowed)
__device__ __half g_h[NS * HID];       // hidden activations (fp16)
__device__ __half g_w1t[HID * DIN];    // W1^T [N,K] fp16
__device__ __half g_w2t[HID * HID];    // W2^T [N,K] fp16
__device__ int    g_idx[NS * 3];
__device__ float  g_w[NS * 3];
__device__ int    g_bstart[BMAX + 1];

// ===========================================================================
// helpers
// ===========================================================================
__device__ __forceinline__ uint32_t h2u(__half2 h) {
    uint32_t u;
    memcpy(&u, &h, 4);
    return u;
}
__device__ __forceinline__ uint32_t smem_u32(const void* p) {
    uint32_t a;
    asm("{ .reg .u64 t; cvta.to.shared.u64 t, %1; cvt.u32.u64 %0, t; }"
        : "=r"(a) : "l"(p));
    return a;
}
__device__ __forceinline__ void cp16(uint32_t sdst, const void* gsrc) {
    asm volatile("cp.async.ca.shared.global [%0], [%1], 16;"
                 :: "r"(sdst), "l"(gsrc));
}
#define CP_COMMIT() asm volatile("cp.async.commit_group;" ::: "memory")
#define CP_WAIT0()  asm volatile("cp.async.wait_group 0;"  ::: "memory")

__device__ __forceinline__ void ldsm4(uint32_t r[4], uint32_t addr) {
    asm volatile("ldmatrix.sync.aligned.m8n8.x4.shared.b16 {%0,%1,%2,%3}, [%4];"
                 : "=r"(r[0]), "=r"(r[1]), "=r"(r[2]), "=r"(r[3]) : "r"(addr));
}
__device__ __forceinline__ void mma_f16(float c[4], const uint32_t a[4],
                                        const uint32_t b0, const uint32_t b1) {
    asm volatile(
        "mma.sync.aligned.m16n8k16.row.col.f32.f16.f16.f32 "
        "{%0,%1,%2,%3}, {%4,%5,%6,%7}, {%8,%9}, {%0,%1,%2,%3};"
        : "+f"(c[0]), "+f"(c[1]), "+f"(c[2]), "+f"(c[3])
        : "r"(a[0]), "r"(a[1]), "r"(a[2]), "r"(a[3]), "r"(b0), "r"(b1));
}

// ===========================================================================
// 1) batch segment boundaries (batch is sorted)
// ===========================================================================
__global__ void seg_kernel(const int* __restrict__ batch, int n) {
    int j = blockIdx.x * blockDim.x + threadIdx.x;
    if (j >= n) return;
    int b  = batch[j];
    int bp = (j == 0) ? -1 : batch[j - 1];
    for (int v = bp + 1; v <= b; v++) g_bstart[v] = j;
    if (j == n - 1) {
        for (int v = b + 1; v <= BMAX; v++) g_bstart[v] = n;
    }
}

// ===========================================================================
// 2) kNN (K=3); block loads only the batch-segment range it needs
// ===========================================================================
__global__ void knn_kernel(const float* __restrict__ pos,
                           const float* __restrict__ pos_skip,
                           const int* __restrict__ batch_skip) {
    extern __shared__ float4 s_pts[];
    int tid = threadIdx.x;
    int t0 = blockIdx.x * blockDim.x;

    int qb_first = batch_skip[t0];
    int qb_last  = batch_skip[t0 + blockDim.x - 1];
    int jmin = g_bstart[qb_first];
    int jmax = g_bstart[qb_last + 1];

    for (int j = jmin + tid; j < jmax; j += blockDim.x) {
        float4 p;
        p.x = pos[3 * j + 0];
        p.y = pos[3 * j + 1];
        p.z = pos[3 * j + 2];
        p.w = 0.0f;
        s_pts[j - jmin] = p;
    }
    __syncthreads();

    int t = t0 + tid;
    float qx = pos_skip[3 * t + 0];
    float qy = pos_skip[3 * t + 1];
    float qz = pos_skip[3 * t + 2];
    int   qb = batch_skip[t];
    int j0 = g_bstart[qb] - jmin;
    int j1 = g_bstart[qb + 1] - jmin;

    float b0 = 3.0e38f, b1 = 3.0e38f, b2 = 3.0e38f;
    int   i0 = j0, i1 = j0, i2 = j0;

    #pragma unroll 4
    for (int j = j0; j < j1; j++) {
        float4 p = s_pts[j];
        float dx = p.x - qx;
        float dy = p.y - qy;
        float dz = p.z - qz;
        float d = fmaf(dx, dx, fmaf(dy, dy, dz * dz));
        if (d < b2) {
            if (d < b1) {
                if (d < b0) {
                    b2 = b1; i2 = i1; b1 = b0; i1 = i0; b0 = d; i0 = j;
                } else {
                    b2 = b1; i2 = i1; b1 = d; i1 = j;
                }
            } else {
                b2 = d; i2 = j;
            }
        }
    }

    float w0 = 1.0f / fmaxf(b0, 1e-16f);
    float w1 = 1.0f / fmaxf(b1, 1e-16f);
    float w2 = 1.0f / fmaxf(b2, 1e-16f);
    float inv = 1.0f / (w0 + w1 + w2);
    g_w[3 * t + 0] = w0 * inv;
    g_w[3 * t + 1] = w1 * inv;
    g_w[3 * t + 2] = w2 * inv;
    g_idx[3 * t + 0] = i0 + jmin;
    g_idx[3 * t + 1] = i1 + jmin;
    g_idx[3 * t + 2] = i2 + jmin;
}

// ===========================================================================
// 3) both weight transposes in ONE launch; fp16 output  W[K,N] -> Wt[N,K]
// ===========================================================================
__global__ void transpose_both(const float* __restrict__ W1, __half* __restrict__ W1t,
                               const float* __restrict__ W2, __half* __restrict__ W2t) {
    __shared__ float tile[32][33];
    const float* W; __half* Wt; int K, k0;
    int bx = blockIdx.x;
    if (bx < DIN / 32) { W = W1; Wt = W1t; K = DIN; k0 = bx * 32; }
    else               { W = W2; Wt = W2t; K = HID; k0 = (bx - DIN / 32) * 32; }
    int n0 = blockIdx.y * 32;
    int tx = threadIdx.x, ty = threadIdx.y;
    for (int i = ty; i < 32; i += 8)
        tile[i][tx] = W[(size_t)(k0 + i) * HID + n0 + tx];
    __syncthreads();
    for (int i = ty; i < 32; i += 8)
        Wt[(size_t)(n0 + i) * K + k0 + tx] = __float2half_rn(tile[tx][i]);
}

// ===========================================================================
// 4) fp16 mma.sync GEMM + bias + ReLU.
//    C[M, 256] = relu(A[M,K] @ Wt^T + bias)
//    FUSED: A built on the fly = [knn-interp(x), x_skip] -> fp16
//    EPI_HALF: store output as fp16 into g_h (feeds next GEMM)
// ===========================================================================
template<int KTOT, bool FUSED, bool EPI_HALF>
__global__ void __launch_bounds__(256, 2)
gemm_mma(const __half* __restrict__ A,
         const float* __restrict__ x,
         const float* __restrict__ xs,
         const __half* __restrict__ Wt,
         const float* __restrict__ bias,
         void* __restrict__ Cv) {
    extern __shared__ char smem[];

    const int tid  = threadIdx.x;
    const int wid  = tid >> 5, lane = tid & 31;
    const int gid  = lane >> 2, tg = lane & 3;
    const int g8   = lane >> 3, r8 = lane & 7;     // ldmatrix lane groups
    const int wm0  = (wid & 3) * 32;               // 4 warps along M
    const int wn0  = (wid >> 2) * 64;              // 2 warps along N
    const int m0   = blockIdx.x * BM;
    const int n0   = blockIdx.y * BN;

    const int lrow  = tid >> 1;                    // 0..127 (row this thread loads)
    const int lkoff = (tid & 1) * 32;              // half offset within BK=64

    int i0 = 0, i1 = 0, i2 = 0;
    float w0 = 0, w1 = 0, w2 = 0;
    if (FUSED) {
        int m = m0 + lrow;
        i0 = g_idx[3 * m]; i1 = g_idx[3 * m + 1]; i2 = g_idx[3 * m + 2];
        w0 = g_w[3 * m];   w1 = g_w[3 * m + 1];   w2 = g_w[3 * m + 2];
    }

    float acc[2][8][4];
    #pragma unroll
    for (int mt = 0; mt < 2; mt++)
        #pragma unroll
        for (int nt = 0; nt < 8; nt++)
            #pragma unroll
            for (int q = 0; q < 4; q++) acc[mt][nt][q] = 0.0f;

    constexpr int T = KTOT / BK;

    auto issue = [&](int t) {
        int s  = t & 1;
        int k0 = t * BK;
        char* dA = smem + s * (2 * STAGEB);
        char* dB = dA + STAGEB;
        // B tile (fp16 weights): 4x cp.async of 16B
        {
            const __half* src = Wt + (size_t)(n0 + lrow) * KTOT + k0 + lkoff;
            uint32_t dst = smem_u32(dB + lrow * ROWB + lkoff * 2);
            #pragma unroll
            for (int j = 0; j < 4; j++) cp16(dst + j * 16, src + j * 8);
        }
        // A tile
        if (FUSED) {
            // build 32 fp32 values, convert to fp16, STS 4x16B
            float v[32];
            #pragma unroll
            for (int h = 0; h < 8; h++) {
                int kg = k0 + lkoff + h * 4;
                float4 vv;
                if (kg < CH) {
                    float4 a0 = *(const float4*)(x + (size_t)i0 * CH + kg);
                    float4 a1 = *(const float4*)(x + (size_t)i1 * CH + kg);
                    float4 a2 = *(const float4*)(x + (size_t)i2 * CH + kg);
                    vv.x = w0 * a0.x + w1 * a1.x + w2 * a2.x;
                    vv.y = w0 * a0.y + w1 * a1.y + w2 * a2.y;
                    vv.z = w0 * a0.z + w1 * a1.z + w2 * a2.z;
                    vv.w = w0 * a0.w + w1 * a1.w + w2 * a2.w;
                } else {
                    vv = *(const float4*)(xs + (size_t)(m0 + lrow) * CSKIP + (kg - CH));
                }
                v[h * 4 + 0] = vv.x; v[h * 4 + 1] = vv.y;
                v[h * 4 + 2] = vv.z; v[h * 4 + 3] = vv.w;
            }
            char* d = dA + lrow * ROWB + lkoff * 2;
            #pragma unroll
            for (int c = 0; c < 4; c++) {
                uint4 u;
                u.x = h2u(__floats2half2_rn(v[c * 8 + 0], v[c * 8 + 1]));
                u.y = h2u(__floats2half2_rn(v[c * 8 + 2], v[c * 8 + 3]));
                u.z = h2u(__floats2half2_rn(v[c * 8 + 4], v[c * 8 + 5]));
                u.w = h2u(__floats2half2_rn(v[c * 8 + 6], v[c * 8 + 7]));
                *(uint4*)(d + c * 16) = u;
            }
        } else {
            const __half* src = A + (size_t)(m0 + lrow) * KTOT + k0 + lkoff;
            uint32_t dst = smem_u32(dA + lrow * ROWB + lkoff * 2);
            #pragma unroll
            for (int j = 0; j < 4; j++) cp16(dst + j * 16, src + j * 8);
        }
    };

    issue(0);
    CP_COMMIT();

    // per-lane ldmatrix base offsets (within a stage)
    // A: matrix g: rows (g&1)*8 + r8, k-chunk (g>>1)*16B
    const uint32_t aLane = (uint32_t)(((g8 & 1) * 8 + r8) * ROWB + (g8 >> 1) * 16);
    // B: matrix g: rows (g>>1)*8 + r8, k-chunk (g&1)*16B
    const uint32_t bLane = (uint32_t)(((g8 >> 1) * 8 + r8) * ROWB + (g8 & 1) * 16);
    const uint32_t sbase = smem_u32(smem);

    for (int t = 0; t < T; t++) {
        CP_WAIT0();
        __syncthreads();
        if (t + 1 < T) { issue(t + 1); CP_COMMIT(); }

        int s = t & 1;
        uint32_t aB0 = sbase + s * (2 * STAGEB) + (uint32_t)(wm0 * ROWB) + aLane;
        uint32_t bB0 = sbase + s * (2 * STAGEB) + STAGEB + (uint32_t)(wn0 * ROWB) + bLane;

        #pragma unroll
        for (int ks = 0; ks < 4; ks++) {          // 4 x k16
            uint32_t koff = ks * 32;              // 16 halfs = 32B
            uint32_t af[2][4];
            #pragma unroll
            for (int mt = 0; mt < 2; mt++)
                ldsm4(af[mt], aB0 + (uint32_t)(mt * 16 * ROWB) + koff);
            uint32_t bf[4][4];
            #pragma unroll
            for (int ntp = 0; ntp < 4; ntp++)
                ldsm4(bf[ntp], bB0 + (uint32_t)(ntp * 16 * ROWB) + koff);
            #pragma unroll
            for (int mt = 0; mt < 2; mt++)
                #pragma unroll
                for (int ntp = 0; ntp < 4; ntp++) {
                    mma_f16(acc[mt][2 * ntp],     af[mt], bf[ntp][0], bf[ntp][1]);
                    mma_f16(acc[mt][2 * ntp + 1], af[mt], bf[ntp][2], bf[ntp][3]);
                }
        }
    }

    // epilogue: bias + relu
    #pragma unroll
    for (int mt = 0; mt < 2; mt++) {
        int r0 = m0 + wm0 + mt * 16 + gid;
        #pragma unroll
        for (int nt = 0; nt < 8; nt++) {
            int col = n0 + wn0 + nt * 8 + tg * 2;
            float bv0 = __ldg(bias + col);
            float bv1 = __ldg(bias + col + 1);
            float v0 = fmaxf(acc[mt][nt][0] + bv0, 0.0f);
            float v1 = fmaxf(acc[mt][nt][1] + bv1, 0.0f);
            float v2 = fmaxf(acc[mt][nt][2] + bv0, 0.0f);
            float v3 = fmaxf(acc[mt][nt][3] + bv1, 0.0f);
            if (EPI_HALF) {
                __half* C = (__half*)Cv;
                *(__half2*)(C + (size_t)r0 * 256 + col)       = __floats2half2_rn(v0, v1);
                *(__half2*)(C + (size_t)(r0 + 8) * 256 + col) = __floats2half2_rn(v2, v3);
            } else {
                float* C = (float*)Cv;
                *(float2*)(C + (size_t)r0 * 256 + col)       = make_float2(v0, v1);
                *(float2*)(C + (size_t)(r0 + 8) * 256 + col) = make_float2(v2, v3);
            }
        }
    }
}

// ===========================================================================
// 5) tuple tail: pos_skip + batch_skip (as float)
// ===========================================================================
__global__ void tail_kernel(const float* __restrict__ pos_skip,
                            const int* __restrict__ batch_skip,
                            float* __restrict__ out, int write_batch) {
    int i = blockIdx.x * blockDim.x + threadIdx.x;
    if (i < NS * 3) out[(size_t)NS * HID + i] = pos_skip[i];
    if (write_batch && i < NS)
        out[(size_t)NS * HID + (size_t)NS * 3 + i] = (float)batch_skip[i];
}

// ===========================================================================
extern "C" void kernel_launch(void* const* d_in, const int* in_sizes, int n_in,
                              void* d_out, int out_size) {
    const float* x          = (const float*)d_in[0];
    const float* pos        = (const float*)d_in[1];
    const int*   batch      = (const int*)  d_in[2];
    const float* x_skip     = (const float*)d_in[3];
    const float* pos_skip   = (const float*)d_in[4];
    const int*   batch_skip = (const int*)  d_in[5];
    const float* W1         = (const float*)d_in[6];
    const float* b1         = (const float*)d_in[7];
    const float* W2         = (const float*)d_in[8];
    const float* b2         = (const float*)d_in[9];
    float* out = (float*)d_out;

    __half *p_h, *p_w1t, *p_w2t;
    cudaGetSymbolAddress((void**)&p_h,   g_h);
    cudaGetSymbolAddress((void**)&p_w1t, g_w1t);
    cudaGetSymbolAddress((void**)&p_w2t, g_w2t);

    // 1) batch segments
    seg_kernel<<<(NPTS + 255) / 256, 256>>>(batch, NPTS);

    // 2) kNN
    size_t knn_smem = (size_t)NPTS * sizeof(float4);
    cudaFuncSetAttribute(knn_kernel, cudaFuncAttributeMaxDynamicSharedMemorySize,
                         (int)knn_smem);
    knn_kernel<<<NS / 128, 128, knn_smem>>>(pos, pos_skip, batch_skip);

    // 3) both weight transposes (fp16), one launch
    {
        dim3 b(32, 8);
        transpose_both<<<dim3(DIN / 32 + HID / 32, HID / 32), b>>>(
            W1, p_w1t, W2, p_w2t);
    }

    // 4) MLP on tensor cores (fp16 mma); GEMM1 fuses interpolate+concat
    cudaFuncSetAttribute(gemm_mma<DIN, true, true>,
                         cudaFuncAttributeMaxDynamicSharedMemorySize, SMEM_GEMM);
    cudaFuncSetAttribute(gemm_mma<HID, false, false>,
                         cudaFuncAttributeMaxDynamicSharedMemorySize, SMEM_GEMM);
    {
        dim3 grid(NS / BM, HID / BN);
        gemm_mma<DIN, true, true><<<grid, 256, SMEM_GEMM>>>(
            nullptr, x, x_skip, p_w1t, b1, (void*)p_h);
        gemm_mma<HID, false, false><<<grid, 256, SMEM_GEMM>>>(
            p_h, nullptr, nullptr, p_w2t, b2, (void*)out);
    }

    // 5) tuple tail
    long long need_pos   = (long long)NS * HID + (long long)NS * 3;
    long long need_batch = need_pos + NS;
    if ((long long)out_size >= need_pos) {
        int wb = ((long long)out_size >= need_batch) ? 1 : 0;
        tail_kernel<<<(NS * 3 + 255) / 256, 256>>>(pos_skip, batch_skip, out, wb);
    }
    (void)n_in; (void)in_sizes;
}